// round 2
// baseline (speedup 1.0000x reference)
#include <cuda_runtime.h>

// Problem constants
#define BATCH 16
#define NPIX  4096            // 64*64
#define CCH   512             // channels
#define MTOT  (BATCH * NPIX)  // 65536

// Scratch (device globals: allocation-free rule)
__device__ float g_q[(size_t)MTOT * CCH];        // 128 MiB
__device__ float g_k[(size_t)MTOT * CCH];        // 128 MiB
__device__ float g_v[(size_t)MTOT * CCH];        // 128 MiB
__device__ float g_s[(size_t)BATCH * CCH * CCH]; // 16 MiB (logits -> softmax in place)

// ---------------------------------------------------------------------------
// Tiling config: 128x128 block tile, BK=8, 256 threads, 8x8 per thread.
// Fragment rows/cols split as [base..base+3] and [base+64..base+67] for
// conflict-free float4 LDS.
// ---------------------------------------------------------------------------
#define BM 128
#define BN 128
#define BK 8

// ---------------------------------------------------------------------------
// Kernel 1: Q/K/V = X @ W + b    (M=65536, N=512, K=512), z selects q/k/v
// ---------------------------------------------------------------------------
__global__ __launch_bounds__(256) void qkv_kernel(
    const float* __restrict__ X,
    const float* __restrict__ Wq, const float* __restrict__ Bq,
    const float* __restrict__ Wk, const float* __restrict__ Bk,
    const float* __restrict__ Wv, const float* __restrict__ Bv)
{
    const float* W; const float* bias; float* outp;
    if (blockIdx.z == 0)      { W = Wq; bias = Bq; outp = g_q; }
    else if (blockIdx.z == 1) { W = Wk; bias = Bk; outp = g_k; }
    else                      { W = Wv; bias = Bv; outp = g_v; }
    float* __restrict__ out = outp;

    __shared__ float As[BK][BM];
    __shared__ float Bs[BK][BN];

    const int tid = threadIdx.x;
    const int bm  = blockIdx.y * BM;
    const int bn  = blockIdx.x * BN;

    // A load: 128 rows x 8 cols, one float4 per thread, transposed store
    const int aRow = tid >> 1;
    const int aCol = (tid & 1) * 4;
    // B load: 8 rows x 128 cols, one float4 per thread
    const int bRow = tid >> 5;
    const int bCol = (tid & 31) * 4;

    const int rowBase = (tid >> 4) * 4;   // 0..60
    const int colBase = (tid & 15) * 4;   // 0..60

    float acc[8][8];
#pragma unroll
    for (int i = 0; i < 8; i++)
#pragma unroll
        for (int j = 0; j < 8; j++) acc[i][j] = 0.f;

    for (int k0 = 0; k0 < CCH; k0 += BK) {
        float4 av = *(const float4*)(X + (size_t)(bm + aRow) * CCH + k0 + aCol);
        As[aCol + 0][aRow] = av.x;
        As[aCol + 1][aRow] = av.y;
        As[aCol + 2][aRow] = av.z;
        As[aCol + 3][aRow] = av.w;
        *(float4*)&Bs[bRow][bCol] =
            *(const float4*)(W + (size_t)(k0 + bRow) * CCH + bn + bCol);
        __syncthreads();
#pragma unroll
        for (int kk = 0; kk < BK; kk++) {
            float ar[8], br[8];
            *(float4*)&ar[0] = *(const float4*)&As[kk][rowBase];
            *(float4*)&ar[4] = *(const float4*)&As[kk][rowBase + 64];
            *(float4*)&br[0] = *(const float4*)&Bs[kk][colBase];
            *(float4*)&br[4] = *(const float4*)&Bs[kk][colBase + 64];
#pragma unroll
            for (int i = 0; i < 8; i++)
#pragma unroll
                for (int j = 0; j < 8; j++) acc[i][j] += ar[i] * br[j];
        }
        __syncthreads();
    }

#pragma unroll
    for (int i = 0; i < 8; i++) {
        const int r = bm + rowBase + (i < 4 ? i : 64 + i - 4);
#pragma unroll
        for (int jh = 0; jh < 2; jh++) {
            const int cb = bn + colBase + (jh ? 64 : 0);
            float4 o;
            o.x = acc[i][jh * 4 + 0] + bias[cb + 0];
            o.y = acc[i][jh * 4 + 1] + bias[cb + 1];
            o.z = acc[i][jh * 4 + 2] + bias[cb + 2];
            o.w = acc[i][jh * 4 + 3] + bias[cb + 3];
            *(float4*)(out + (size_t)r * CCH + cb) = o;
        }
    }
}

// ---------------------------------------------------------------------------
// Kernel 2: S[b] = Q[b]^T @ K[b]   (M=512, N=512, Kdim=4096), z = batch
// Both operands are (n, c) row-major == K-major: no transpose needed.
// ---------------------------------------------------------------------------
__global__ __launch_bounds__(256) void s_kernel()
{
    const int b = blockIdx.z;
    const float* __restrict__ Q = g_q + (size_t)b * NPIX * CCH;
    const float* __restrict__ K = g_k + (size_t)b * NPIX * CCH;
    float* __restrict__ S = g_s + (size_t)b * CCH * CCH;

    __shared__ float As[BK][BM];
    __shared__ float Bs[BK][BN];

    const int tid = threadIdx.x;
    const int bm  = blockIdx.y * BM;
    const int bn  = blockIdx.x * BN;

    const int lRow = tid >> 5;
    const int lCol = (tid & 31) * 4;

    const int rowBase = (tid >> 4) * 4;
    const int colBase = (tid & 15) * 4;

    float acc[8][8];
#pragma unroll
    for (int i = 0; i < 8; i++)
#pragma unroll
        for (int j = 0; j < 8; j++) acc[i][j] = 0.f;

    for (int k0 = 0; k0 < NPIX; k0 += BK) {
        *(float4*)&As[lRow][lCol] =
            *(const float4*)(Q + (size_t)(k0 + lRow) * CCH + bm + lCol);
        *(float4*)&Bs[lRow][lCol] =
            *(const float4*)(K + (size_t)(k0 + lRow) * CCH + bn + lCol);
        __syncthreads();
#pragma unroll
        for (int kk = 0; kk < BK; kk++) {
            float ar[8], br[8];
            *(float4*)&ar[0] = *(const float4*)&As[kk][rowBase];
            *(float4*)&ar[4] = *(const float4*)&As[kk][rowBase + 64];
            *(float4*)&br[0] = *(const float4*)&Bs[kk][colBase];
            *(float4*)&br[4] = *(const float4*)&Bs[kk][colBase + 64];
#pragma unroll
            for (int i = 0; i < 8; i++)
#pragma unroll
                for (int j = 0; j < 8; j++) acc[i][j] += ar[i] * br[j];
        }
        __syncthreads();
    }

#pragma unroll
    for (int i = 0; i < 8; i++) {
        const int r = bm + rowBase + (i < 4 ? i : 64 + i - 4);
#pragma unroll
        for (int jh = 0; jh < 2; jh++) {
            const int cb = bn + colBase + (jh ? 64 : 0);
            float4 o;
            o.x = acc[i][jh * 4 + 0];
            o.y = acc[i][jh * 4 + 1];
            o.z = acc[i][jh * 4 + 2];
            o.w = acc[i][jh * 4 + 3];
            *(float4*)(S + (size_t)r * CCH + cb) = o;
        }
    }
}

// ---------------------------------------------------------------------------
// Kernel 3: row softmax over last dim of S (8192 rows of 512), in place.
// Warp-shuffle reduction: 256 threads, 2 elements each.
// ---------------------------------------------------------------------------
__global__ __launch_bounds__(256) void softmax_kernel()
{
    float* __restrict__ row = g_s + (size_t)blockIdx.x * CCH;
    __shared__ float red[8];
    const int t    = threadIdx.x;
    const int lane = t & 31;
    const int wid  = t >> 5;

    const float v0 = row[t];
    const float v1 = row[t + 256];

    // max reduce
    float m = fmaxf(v0, v1);
#pragma unroll
    for (int o = 16; o > 0; o >>= 1)
        m = fmaxf(m, __shfl_xor_sync(0xffffffffu, m, o));
    if (lane == 0) red[wid] = m;
    __syncthreads();
    m = red[lane & 7];
#pragma unroll
    for (int o = 4; o > 0; o >>= 1)
        m = fmaxf(m, __shfl_xor_sync(0xffffffffu, m, o));
    const float mx = __shfl_sync(0xffffffffu, m, 0);

    const float e0 = expf(v0 - mx);
    const float e1 = expf(v1 - mx);

    // sum reduce
    float s = e0 + e1;
#pragma unroll
    for (int o = 16; o > 0; o >>= 1)
        s += __shfl_xor_sync(0xffffffffu, s, o);
    __syncthreads();   // protect red[] reuse
    if (lane == 0) red[wid] = s;
    __syncthreads();
    s = red[lane & 7];
#pragma unroll
    for (int o = 4; o > 0; o >>= 1)
        s += __shfl_xor_sync(0xffffffffu, s, o);
    const float inv = 1.0f / __shfl_sync(0xffffffffu, s, 0);

    row[t]       = e0 * inv;
    row[t + 256] = e1 * inv;
}

// ---------------------------------------------------------------------------
// Kernel 4: out[b] = x[b] + gamma * (V[b] @ A[b])
// (M=4096 per batch, N=512, Kdim=512); V row-major MxK (transpose load),
// A row-major KxN. z = batch.
// ---------------------------------------------------------------------------
__global__ __launch_bounds__(256) void out_kernel(
    const float* __restrict__ X,
    const float* __restrict__ gamma,
    float* __restrict__ Out)
{
    const int b = blockIdx.z;
    const float* __restrict__ V = g_v + (size_t)b * NPIX * CCH;
    const float* __restrict__ A = g_s + (size_t)b * CCH * CCH;

    __shared__ float As[BK][BM];
    __shared__ float Bs[BK][BN];

    const int tid = threadIdx.x;
    const int bm  = blockIdx.y * BM;
    const int bn  = blockIdx.x * BN;

    const int aRow = tid >> 1;
    const int aCol = (tid & 1) * 4;
    const int bRow = tid >> 5;
    const int bCol = (tid & 31) * 4;

    const int rowBase = (tid >> 4) * 4;
    const int colBase = (tid & 15) * 4;

    float acc[8][8];
#pragma unroll
    for (int i = 0; i < 8; i++)
#pragma unroll
        for (int j = 0; j < 8; j++) acc[i][j] = 0.f;

    for (int k0 = 0; k0 < CCH; k0 += BK) {
        float4 av = *(const float4*)(V + (size_t)(bm + aRow) * CCH + k0 + aCol);
        As[aCol + 0][aRow] = av.x;
        As[aCol + 1][aRow] = av.y;
        As[aCol + 2][aRow] = av.z;
        As[aCol + 3][aRow] = av.w;
        *(float4*)&Bs[bRow][bCol] =
            *(const float4*)(A + (size_t)(k0 + bRow) * CCH + bn + bCol);
        __syncthreads();
#pragma unroll
        for (int kk = 0; kk < BK; kk++) {
            float ar[8], br[8];
            *(float4*)&ar[0] = *(const float4*)&As[kk][rowBase];
            *(float4*)&ar[4] = *(const float4*)&As[kk][rowBase + 64];
            *(float4*)&br[0] = *(const float4*)&Bs[kk][colBase];
            *(float4*)&br[4] = *(const float4*)&Bs[kk][colBase + 64];
#pragma unroll
            for (int i = 0; i < 8; i++)
#pragma unroll
                for (int j = 0; j < 8; j++) acc[i][j] += ar[i] * br[j];
        }
        __syncthreads();
    }

    const float g = gamma[0];
#pragma unroll
    for (int i = 0; i < 8; i++) {
        const int r = bm + rowBase + (i < 4 ? i : 64 + i - 4);
        const size_t rowOff = ((size_t)b * NPIX + r) * CCH;
#pragma unroll
        for (int jh = 0; jh < 2; jh++) {
            const int cb = bn + colBase + (jh ? 64 : 0);
            const float4 xi = *(const float4*)(X + rowOff + cb);
            float4 o;
            o.x = xi.x + g * acc[i][jh * 4 + 0];
            o.y = xi.y + g * acc[i][jh * 4 + 1];
            o.z = xi.z + g * acc[i][jh * 4 + 2];
            o.w = xi.w + g * acc[i][jh * 4 + 3];
            *(float4*)(Out + rowOff + cb) = o;
        }
    }
}

// ---------------------------------------------------------------------------
extern "C" void kernel_launch(void* const* d_in, const int* in_sizes, int n_in,
                              void* d_out, int out_size)
{
    const float* x     = (const float*)d_in[0];
    const float* wq    = (const float*)d_in[1];
    const float* bq    = (const float*)d_in[2];
    const float* wk    = (const float*)d_in[3];
    const float* bk    = (const float*)d_in[4];
    const float* wv    = (const float*)d_in[5];
    const float* bv    = (const float*)d_in[6];
    const float* gamma = (const float*)d_in[7];
    float* out = (float*)d_out;

    // Q/K/V projections: grid (4, 512, 3)
    qkv_kernel<<<dim3(CCH / BN, MTOT / BM, 3), 256>>>(x, wq, bq, wk, bk, wv, bv);
    // S = Q^T K per batch: grid (4, 4, 16)
    s_kernel<<<dim3(CCH / BN, CCH / BM, BATCH), 256>>>();
    // softmax over rows: 16*512 rows
    softmax_kernel<<<BATCH * CCH, 256>>>();
    // out = x + gamma * V @ A : grid (4, 32, 16)
    out_kernel<<<dim3(CCH / BN, NPIX / BM, BATCH), 256>>>(x, gamma, out);
}

// round 4
// speedup vs baseline: 1.3135x; 1.3135x over previous
#include <cuda_runtime.h>
#include <cuda_bf16.h>
#include <cstdint>
#include <cstddef>
#include <cstring>

#define BATCH 16
#define NPIX  4096
#define CCH   512
#define MTOT  (BATCH * NPIX)   // 65536

typedef __nv_bfloat16 bf16;

#define SZX  ((size_t)MTOT * CCH)        // 33,554,432 elems
#define SZW  ((size_t)CCH * CCH)         // 262,144
#define SZS  ((size_t)BATCH * CCH * CCH) // 4,194,304

__device__ bf16  g_x [3 * SZX];          // x splits (hi, mid, lo)
__device__ bf16  g_wt[9 * SZW];          // [w(q,k,v)][term] transposed weight splits
__device__ bf16  g_qt[3 * SZX];          // q transposed splits: per batch [c][n]
__device__ bf16  g_kt[3 * SZX];          // k transposed splits
__device__ bf16  g_v [2 * SZX];          // v splits: [n][c]
__device__ float g_st[SZS];              // S transposed fp32: per batch [d][c]
__device__ bf16  g_at[2 * SZS];          // softmax(A) transposed splits: [d][c]

// ---------------------------------------------------------------------------
__device__ __forceinline__ uint32_t smem_u32(const void* p) {
    uint32_t a;
    asm("{ .reg .u64 t; cvta.to.shared.u64 t, %1; cvt.u32.u64 %0, t; }"
        : "=r"(a) : "l"(p));
    return a;
}

__device__ __forceinline__ void cp16(uint32_t dst, const void* src) {
    asm volatile("cp.async.cg.shared.global [%0], [%1], 16;" :: "r"(dst), "l"(src) : "memory");
}

__device__ __forceinline__ void ldsm_x4(uint32_t* r, uint32_t addr) {
    asm volatile("ldmatrix.sync.aligned.m8n8.x4.shared.b16 {%0,%1,%2,%3}, [%4];"
        : "=r"(r[0]), "=r"(r[1]), "=r"(r[2]), "=r"(r[3]) : "r"(addr));
}

__device__ __forceinline__ void mma16816(float* c, const uint32_t* a, const uint32_t* b) {
    asm volatile(
        "mma.sync.aligned.m16n8k16.row.col.f32.bf16.bf16.f32 "
        "{%0,%1,%2,%3}, {%4,%5,%6,%7}, {%8,%9}, {%0,%1,%2,%3};"
        : "+f"(c[0]), "+f"(c[1]), "+f"(c[2]), "+f"(c[3])
        : "r"(a[0]), "r"(a[1]), "r"(a[2]), "r"(a[3]), "r"(b[0]), "r"(b[1]));
}

__device__ __forceinline__ uint32_t pack_bf2(float a, float b) {
    __nv_bfloat162 t = __floats2bfloat162_rn(a, b);
    uint32_t u; memcpy(&u, &t, 4); return u;
}

__device__ __forceinline__ void split3(float v, float& h, float& m, float& l) {
    h = __bfloat162float(__float2bfloat16(v));
    float r = v - h;
    m = __bfloat162float(__float2bfloat16(r));
    l = r - m;
}

// ---------------------------------------------------------------------------
// Split kernels
// ---------------------------------------------------------------------------
__global__ __launch_bounds__(256) void split_x_kernel(const float* __restrict__ x)
{
    size_t i4 = (size_t)blockIdx.x * 256 + threadIdx.x;
    const float4 v = ((const float4*)x)[i4];
    float h[4], m[4], l[4];
    split3(v.x, h[0], m[0], l[0]); split3(v.y, h[1], m[1], l[1]);
    split3(v.z, h[2], m[2], l[2]); split3(v.w, h[3], m[3], l[3]);
    uint32_t* o0 = (uint32_t*)g_x;
    uint32_t* o1 = (uint32_t*)(g_x + SZX);
    uint32_t* o2 = (uint32_t*)(g_x + 2 * SZX);
    o0[i4*2] = pack_bf2(h[0], h[1]); o0[i4*2+1] = pack_bf2(h[2], h[3]);
    o1[i4*2] = pack_bf2(m[0], m[1]); o1[i4*2+1] = pack_bf2(m[2], m[3]);
    o2[i4*2] = pack_bf2(l[0], l[1]); o2[i4*2+1] = pack_bf2(l[2], l[3]);
}

__global__ __launch_bounds__(256) void split_w_kernel(
    const float* __restrict__ wq, const float* __restrict__ wk, const float* __restrict__ wv)
{
    __shared__ float tile[32][33];
    const int z = blockIdx.z;
    const float* w = (z == 0) ? wq : (z == 1) ? wk : wv;
    bf16* out = g_wt + (size_t)z * 3 * SZW;
    const int f0 = blockIdx.x * 32, c0 = blockIdx.y * 32;
    const int tx = threadIdx.x & 31, ty = threadIdx.x >> 5;
#pragma unroll
    for (int k = 0; k < 4; k++)
        tile[ty + 8*k][tx] = w[(size_t)(c0 + ty + 8*k) * CCH + f0 + tx];
    __syncthreads();
#pragma unroll
    for (int k = 0; k < 4; k++) {
        const int fl = ty + 8*k;
        float v = tile[tx][fl];
        float h, m, l; split3(v, h, m, l);
        size_t idx = (size_t)(f0 + fl) * CCH + c0 + tx;
        out[idx]         = __float2bfloat16(h);
        out[SZW + idx]   = __float2bfloat16(m);
        out[2*SZW + idx] = __float2bfloat16(l);
    }
}

// ---------------------------------------------------------------------------
// mma.sync GEMM: 128x128 tile, 256 threads (warp grid 4x2, 32x64 per warp),
// K-chunk 32, double-buffered cp.async. A,B tiles K-major [row][k], smem
// stride 40 bf16 (80B).
// EPI: 0=QK (bias+transpose+3split), 1=V (bias+2split), 2=S (transpose fp32),
//      3=OUT (x + gamma*acc)
// ---------------------------------------------------------------------------
#define TSTRIDE 40           // bf16 elems per smem row
#define TILEB   (128 * TSTRIDE * 2)   // 10240 bytes per tile

template<int TA, int TB, int NP, int EPI>
__global__ __launch_bounds__(256, 1) void gemm_mma(
    const bf16* __restrict__ A0, const bf16* __restrict__ A1, const bf16* __restrict__ A2,
    const bf16* __restrict__ B0, const bf16* __restrict__ B1, const bf16* __restrict__ B2,
    long aStride, long bStride, int Kdim,
    const float* __restrict__ bias,
    const float* __restrict__ Xres, const float* __restrict__ gammap,
    void* O0, void* O1, void* O2)
{
    constexpr int NT = TA + TB;
    constexpr int AIx[6] = {0, 0, 1, 1, 0, 2};
    constexpr int BIx[6] = {0, 1, 0, 1, 2, 0};

    extern __shared__ char smem[];
    const uint32_t sb = smem_u32(smem);
    const int tid  = threadIdx.x;
    const int lane = tid & 31;
    const int wid  = tid >> 5;
    const int wm   = wid & 3;        // 0..3  (M direction, 32 rows each)
    const int wn   = wid >> 2;       // 0..1  (N direction, 64 cols each)

    const size_t aOff = (size_t)blockIdx.z * aStride + (size_t)blockIdx.y * 128 * Kdim;
    const size_t bOff = (size_t)blockIdx.z * bStride + (size_t)blockIdx.x * 128 * Kdim;
    const bf16* tp[NT];
    tp[0] = A0 + aOff;
    if (TA > 1) tp[1] = A1 + aOff;
    if (TA > 2) tp[2] = A2 + aOff;
    tp[TA] = B0 + bOff;
    if (TB > 1) tp[TA + 1] = B1 + bOff;
    if (TB > 2) tp[TA + 2] = B2 + bOff;

    const int nc = Kdim >> 5;        // chunks of 32

    auto load_chunk = [&](int c) {
        const uint32_t sbase = sb + (uint32_t)(c & 1) * NT * TILEB;
        const int k0 = c << 5;
#pragma unroll
        for (int t = 0; t < NT; t++) {
            const bf16* gp = tp[t] + k0;
            const uint32_t tb = sbase + t * TILEB;
#pragma unroll
            for (int i = 0; i < 2; i++) {
                const int idx = i * 256 + tid;
                const int r = idx >> 2, q = idx & 3;
                cp16(tb + r * (TSTRIDE * 2) + q * 16, gp + (size_t)r * Kdim + q * 8);
            }
        }
        asm volatile("cp.async.commit_group;" ::: "memory");
    };

    float acc[2][8][4];
#pragma unroll
    for (int mt = 0; mt < 2; mt++)
#pragma unroll
        for (int nt = 0; nt < 8; nt++)
#pragma unroll
            for (int e = 0; e < 4; e++) acc[mt][nt][e] = 0.f;

    // ldmatrix smem address offsets (within a tile)
    const uint32_t aAddrOff = (uint32_t)(wm * 32 + (lane & 15)) * (TSTRIDE * 2)
                            + (uint32_t)(lane >> 4) * 16;          // + mt*16 rows, + kk*32 bytes
    const uint32_t bAddrOff = (uint32_t)(wn * 64 + (lane & 7) + ((lane >> 4) & 1) * 8) * (TSTRIDE * 2)
                            + (uint32_t)((lane >> 3) & 1) * 16;    // + p*16 rows, + kk*32 bytes

    load_chunk(0);
    for (int c = 0; c < nc; c++) {
        if (c + 1 < nc) {
            load_chunk(c + 1);
            asm volatile("cp.async.wait_group 1;" ::: "memory");
        } else {
            asm volatile("cp.async.wait_group 0;" ::: "memory");
        }
        __syncthreads();

        const uint32_t sbase = sb + (uint32_t)(c & 1) * NT * TILEB;
#pragma unroll
        for (int kk = 0; kk < 2; kk++) {
            uint32_t af[TA][2][4];
            uint32_t bfr[TB][4][4];
#pragma unroll
            for (int t = 0; t < TA; t++)
#pragma unroll
                for (int mt = 0; mt < 2; mt++)
                    ldsm_x4(af[t][mt],
                            sbase + t * TILEB + aAddrOff + (uint32_t)mt * 16 * (TSTRIDE * 2) + kk * 32);
#pragma unroll
            for (int t = 0; t < TB; t++)
#pragma unroll
                for (int p = 0; p < 4; p++)
                    ldsm_x4(bfr[t][p],
                            sbase + (TA + t) * TILEB + bAddrOff + (uint32_t)p * 16 * (TSTRIDE * 2) + kk * 32);
#pragma unroll
            for (int p = 0; p < NP; p++)
#pragma unroll
                for (int mt = 0; mt < 2; mt++)
#pragma unroll
                    for (int pq = 0; pq < 4; pq++) {
                        mma16816(acc[mt][pq * 2 + 0], af[AIx[p]][mt], &bfr[BIx[p]][pq][0]);
                        mma16816(acc[mt][pq * 2 + 1], af[AIx[p]][mt], &bfr[BIx[p]][pq][2]);
                    }
        }
        __syncthreads();
    }

    // -----------------------------------------------------------------------
    // Epilogues. Fragment (mt,nt): c0,c1 at (row, col),(row,col+1); c2,c3 at
    // row+8. row = wm*32+mt*16+lane/4, col = wn*64+nt*8+(lane%4)*2.
    // -----------------------------------------------------------------------
    const int fr = wm * 32 + (lane >> 2);
    const int fc = wn * 64 + (lane & 3) * 2;

    if (EPI == 1) {
        bf16* q0 = (bf16*)O0; bf16* q1 = (bf16*)O1;
#pragma unroll
        for (int mt = 0; mt < 2; mt++)
#pragma unroll
            for (int nt = 0; nt < 8; nt++)
#pragma unroll
                for (int h = 0; h < 2; h++) {
                    const int row = fr + mt * 16 + h * 8;
                    const int col = fc + nt * 8;
                    const int gcol = blockIdx.x * 128 + col;
                    float v0 = acc[mt][nt][h * 2 + 0] + bias[gcol];
                    float v1 = acc[mt][nt][h * 2 + 1] + bias[gcol + 1];
                    float h0 = __bfloat162float(__float2bfloat16(v0));
                    float h1 = __bfloat162float(__float2bfloat16(v1));
                    const size_t e = ((size_t)blockIdx.y * 128 + row) * CCH + gcol;
                    *(uint32_t*)(q0 + e) = pack_bf2(h0, h1);
                    *(uint32_t*)(q1 + e) = pack_bf2(v0 - h0, v1 - h1);
                }
    } else if (EPI == 3) {
        const float g = gammap[0];
        float* Op = (float*)O0;
#pragma unroll
        for (int mt = 0; mt < 2; mt++)
#pragma unroll
            for (int nt = 0; nt < 8; nt++)
#pragma unroll
                for (int h = 0; h < 2; h++) {
                    const int row = fr + mt * 16 + h * 8;
                    const int col = fc + nt * 8;
                    const size_t nrow = (size_t)blockIdx.z * NPIX + (size_t)blockIdx.y * 128 + row;
                    const size_t e = nrow * CCH + blockIdx.x * 128 + col;
                    const float2 xi = *(const float2*)(Xres + e);
                    float2 o;
                    o.x = xi.x + g * acc[mt][nt][h * 2 + 0];
                    o.y = xi.y + g * acc[mt][nt][h * 2 + 1];
                    *(float2*)(Op + e) = o;
                }
    } else {
        // transpose epilogues via fp32 smem buffer [128][132]
        float* sbuf = (float*)smem;
#pragma unroll
        for (int mt = 0; mt < 2; mt++)
#pragma unroll
            for (int nt = 0; nt < 8; nt++)
#pragma unroll
                for (int h = 0; h < 2; h++) {
                    const int row = fr + mt * 16 + h * 8;
                    const int col = fc + nt * 8;
                    float v0 = acc[mt][nt][h * 2 + 0];
                    float v1 = acc[mt][nt][h * 2 + 1];
                    if (EPI == 0) {
                        v0 += bias[blockIdx.x * 128 + col];
                        v1 += bias[blockIdx.x * 128 + col + 1];
                    }
                    sbuf[row * 132 + col]     = v0;
                    sbuf[row * 132 + col + 1] = v1;
                }
        __syncthreads();

        const int pr      = (tid & 63) * 2;  // source row pair
        const int quarter = tid >> 6;        // 0..3, 32 output cols each
        if (EPI == 0) {
            const int bch = (blockIdx.y * 128) >> 12;
            const int n0  = (blockIdx.y * 128) & 4095;
            bf16* q0 = (bf16*)O0; bf16* q1 = (bf16*)O1; bf16* q2 = (bf16*)O2;
#pragma unroll 8
            for (int ff = 0; ff < 32; ff++) {
                const int fl = quarter * 32 + ff;
                const float v0 = sbuf[pr * 132 + fl];
                const float v1 = sbuf[(pr + 1) * 132 + fl];
                float h0, m0, l0, h1, m1, l1;
                split3(v0, h0, m0, l0); split3(v1, h1, m1, l1);
                const size_t e = ((size_t)bch * CCH + blockIdx.x * 128 + fl) * NPIX + n0 + pr;
                *(uint32_t*)(q0 + e) = pack_bf2(h0, h1);
                *(uint32_t*)(q1 + e) = pack_bf2(m0, m1);
                *(uint32_t*)(q2 + e) = pack_bf2(l0, l1);
            }
        } else { // EPI == 2
            float* st = (float*)O0;
#pragma unroll 8
            for (int dd = 0; dd < 32; dd++) {
                const int dl = quarter * 32 + dd;
                float2 o;
                o.x = sbuf[pr * 132 + dl];
                o.y = sbuf[(pr + 1) * 132 + dl];
                const size_t e = (size_t)blockIdx.z * SZW +
                                 (size_t)(blockIdx.x * 128 + dl) * CCH +
                                 blockIdx.y * 128 + pr;
                *(float2*)(st + e) = o;
            }
        }
    }
}

// ---------------------------------------------------------------------------
// Column softmax on S_t [d][c] (softmax over d), writes 2-split A_t [d][c]
// ---------------------------------------------------------------------------
__global__ __launch_bounds__(128) void softmax_col_kernel()
{
    const int b = blockIdx.y;
    const int c = blockIdx.x * 128 + threadIdx.x;
    const float* S = g_st + (size_t)b * SZW;
    bf16* a0 = g_at + (size_t)b * SZW;
    bf16* a1 = g_at + SZS + (size_t)b * SZW;

    float m = -1e30f;
    for (int d = 0; d < CCH; d++) m = fmaxf(m, S[(size_t)d * CCH + c]);
    float s = 0.f;
    for (int d = 0; d < CCH; d++) s += expf(S[(size_t)d * CCH + c] - m);
    const float inv = 1.0f / s;
    for (int d = 0; d < CCH; d++) {
        const float p = expf(S[(size_t)d * CCH + c] - m) * inv;
        const float h = __bfloat162float(__float2bfloat16(p));
        a0[(size_t)d * CCH + c] = __float2bfloat16(h);
        a1[(size_t)d * CCH + c] = __float2bfloat16(p - h);
    }
}

// ---------------------------------------------------------------------------
extern "C" void kernel_launch(void* const* d_in, const int* in_sizes, int n_in,
                              void* d_out, int out_size)
{
    const float* x     = (const float*)d_in[0];
    const float* wq    = (const float*)d_in[1];
    const float* bq    = (const float*)d_in[2];
    const float* wk    = (const float*)d_in[3];
    const float* bk    = (const float*)d_in[4];
    const float* wv    = (const float*)d_in[5];
    const float* bv    = (const float*)d_in[6];
    const float* gamma = (const float*)d_in[7];
    float* out = (float*)d_out;

    void* p;
    cudaGetSymbolAddress(&p, g_x);  bf16* xs = (bf16*)p;
    cudaGetSymbolAddress(&p, g_wt); bf16* wt = (bf16*)p;
    cudaGetSymbolAddress(&p, g_qt); bf16* qt = (bf16*)p;
    cudaGetSymbolAddress(&p, g_kt); bf16* kt = (bf16*)p;
    cudaGetSymbolAddress(&p, g_v);  bf16* vs = (bf16*)p;
    cudaGetSymbolAddress(&p, g_st); float* st = (float*)p;
    cudaGetSymbolAddress(&p, g_at); bf16* at = (bf16*)p;

    const int SM3 = 2 * 6 * TILEB;   // 122880
    const int SM2 = 2 * 4 * TILEB;   // 81920
    cudaFuncSetAttribute(gemm_mma<3,3,6,0>, cudaFuncAttributeMaxDynamicSharedMemorySize, SM3);
    cudaFuncSetAttribute(gemm_mma<2,2,3,1>, cudaFuncAttributeMaxDynamicSharedMemorySize, SM2);
    cudaFuncSetAttribute(gemm_mma<3,3,6,2>, cudaFuncAttributeMaxDynamicSharedMemorySize, SM3);
    cudaFuncSetAttribute(gemm_mma<2,2,3,3>, cudaFuncAttributeMaxDynamicSharedMemorySize, SM2);

    // 1) splits
    split_x_kernel<<<(unsigned)(SZX / 4 / 256), 256>>>(x);
    split_w_kernel<<<dim3(16, 16, 3), 256>>>(wq, wk, wv);

    // 2) Q = X@Wq^T (3-term, transpose epilogue -> q_t splits)
    gemm_mma<3,3,6,0><<<dim3(4, 512, 1), 256, SM3>>>(
        xs, xs + SZX, xs + 2*SZX,
        wt + 0*3*SZW, wt + 0*3*SZW + SZW, wt + 0*3*SZW + 2*SZW,
        0, 0, CCH, bq, nullptr, nullptr,
        qt, qt + SZX, qt + 2*SZX);
    // 3) K
    gemm_mma<3,3,6,0><<<dim3(4, 512, 1), 256, SM3>>>(
        xs, xs + SZX, xs + 2*SZX,
        wt + 1*3*SZW, wt + 1*3*SZW + SZW, wt + 1*3*SZW + 2*SZW,
        0, 0, CCH, bk, nullptr, nullptr,
        kt, kt + SZX, kt + 2*SZX);
    // 4) V (2-term, direct epilogue)
    gemm_mma<2,2,3,1><<<dim3(4, 512, 1), 256, SM2>>>(
        xs, xs + SZX, nullptr,
        wt + 2*3*SZW, wt + 2*3*SZW + SZW, nullptr,
        0, 0, CCH, bv, nullptr, nullptr,
        vs, vs + SZX, nullptr);
    // 5) S = Q^T K per batch (Kdim=4096), transpose epilogue -> S_t fp32
    gemm_mma<3,3,6,2><<<dim3(4, 4, BATCH), 256, SM3>>>(
        qt, qt + SZX, qt + 2*SZX,
        kt, kt + SZX, kt + 2*SZX,
        (long)CCH * NPIX, (long)CCH * NPIX, NPIX, nullptr, nullptr, nullptr,
        st, nullptr, nullptr);
    // 6) column softmax -> A_t splits
    softmax_col_kernel<<<dim3(4, BATCH), 128>>>();
    // 7) out = x + gamma * V @ A (2-term, fused residual epilogue)
    gemm_mma<2,2,3,3><<<dim3(4, 32, BATCH), 256, SM2>>>(
        vs, vs + SZX, nullptr,
        at, at + SZS, nullptr,
        (long)NPIX * CCH, (long)CCH * CCH, CCH, nullptr, x, gamma,
        out, nullptr, nullptr);
}

// round 5
// speedup vs baseline: 1.6724x; 1.2732x over previous
#include <cuda_runtime.h>
#include <cuda_fp16.h>
#include <cstdint>
#include <cstddef>
#include <cstring>

#define BATCH 16
#define NPIX  4096
#define CCH   512
#define MTOT  (BATCH * NPIX)   // 65536

typedef __half h16;

#define SZX  ((size_t)MTOT * CCH)        // 33,554,432 elems
#define SZW  ((size_t)CCH * CCH)         // 262,144
#define SZS  ((size_t)BATCH * CCH * CCH) // 4,194,304

// fp16 split planes
__device__ h16   g_x [3 * SZX];          // x: {h, h*2^-11, m}
__device__ h16   g_wt[3 * 2 * SZW];      // per matrix {h, m*2^11}, transposed
__device__ h16   g_qt[2 * SZX];          // q_t per batch [c][n]: {h, m}
__device__ h16   g_kt[2 * SZX];          // k_t: {h, m}
__device__ h16   g_v [3 * SZX];          // v [n][c]: {h, h*2^-11, m}
__device__ float g_st[SZS];              // S_t fp32 per batch [d][c]
__device__ h16   g_at[2 * SZS];          // a_t [d][c]: {h, m*2^11}

#define SC_DN 4.8828125e-4f   // 2^-11
#define SC_UP 2048.0f         // 2^11

// ---------------------------------------------------------------------------
__device__ __forceinline__ uint32_t smem_u32(const void* p) {
    uint32_t a;
    asm("{ .reg .u64 t; cvta.to.shared.u64 t, %1; cvt.u32.u64 %0, t; }"
        : "=r"(a) : "l"(p));
    return a;
}

__device__ __forceinline__ void cp16(uint32_t dst, const void* src) {
    asm volatile("cp.async.cg.shared.global [%0], [%1], 16;" :: "r"(dst), "l"(src) : "memory");
}

__device__ __forceinline__ void ldsm_x4(uint32_t* r, uint32_t addr) {
    asm volatile("ldmatrix.sync.aligned.m8n8.x4.shared.b16 {%0,%1,%2,%3}, [%4];"
        : "=r"(r[0]), "=r"(r[1]), "=r"(r[2]), "=r"(r[3]) : "r"(addr));
}

__device__ __forceinline__ void mma16816(float* c, const uint32_t* a, const uint32_t* b) {
    asm volatile(
        "mma.sync.aligned.m16n8k16.row.col.f32.f16.f16.f32 "
        "{%0,%1,%2,%3}, {%4,%5,%6,%7}, {%8,%9}, {%0,%1,%2,%3};"
        : "+f"(c[0]), "+f"(c[1]), "+f"(c[2]), "+f"(c[3])
        : "r"(a[0]), "r"(a[1]), "r"(a[2]), "r"(a[3]), "r"(b[0]), "r"(b[1]));
}

__device__ __forceinline__ uint32_t pack_h2(float a, float b) {
    __half2 t = __floats2half2_rn(a, b);
    uint32_t u; memcpy(&u, &t, 4); return u;
}

// ---------------------------------------------------------------------------
// Split kernels
// ---------------------------------------------------------------------------
__global__ __launch_bounds__(256) void split_x_kernel(const float* __restrict__ x)
{
    size_t i4 = (size_t)blockIdx.x * 256 + threadIdx.x;
    const float4 v = ((const float4*)x)[i4];
    float vv[4] = {v.x, v.y, v.z, v.w};
    float hf[4], hd[4], mf[4];
#pragma unroll
    for (int i = 0; i < 4; i++) {
        hf[i] = __half2float(__float2half_rn(vv[i]));
        hd[i] = hf[i] * SC_DN;
        mf[i] = vv[i] - hf[i];
    }
    uint32_t* o0 = (uint32_t*)g_x;
    uint32_t* o1 = (uint32_t*)(g_x + SZX);
    uint32_t* o2 = (uint32_t*)(g_x + 2 * SZX);
    o0[i4*2] = pack_h2(hf[0], hf[1]); o0[i4*2+1] = pack_h2(hf[2], hf[3]);
    o1[i4*2] = pack_h2(hd[0], hd[1]); o1[i4*2+1] = pack_h2(hd[2], hd[3]);
    o2[i4*2] = pack_h2(mf[0], mf[1]); o2[i4*2+1] = pack_h2(mf[2], mf[3]);
}

// transpose + 2-plane split {h, m*2^11} of the three weight matrices
__global__ __launch_bounds__(256) void split_w_kernel(
    const float* __restrict__ wq, const float* __restrict__ wk, const float* __restrict__ wv)
{
    __shared__ float tile[32][33];
    const int z = blockIdx.z;
    const float* w = (z == 0) ? wq : (z == 1) ? wk : wv;
    h16* out = g_wt + (size_t)z * 2 * SZW;
    const int f0 = blockIdx.x * 32, c0 = blockIdx.y * 32;
    const int tx = threadIdx.x & 31, ty = threadIdx.x >> 5;
#pragma unroll
    for (int k = 0; k < 4; k++)
        tile[ty + 8*k][tx] = w[(size_t)(c0 + ty + 8*k) * CCH + f0 + tx];
    __syncthreads();
#pragma unroll
    for (int k = 0; k < 4; k++) {
        const int fl = ty + 8*k;
        float v = tile[tx][fl];
        float hf = __half2float(__float2half_rn(v));
        size_t idx = (size_t)(f0 + fl) * CCH + c0 + tx;
        out[idx]       = __float2half_rn(hf);
        out[SZW + idx] = __float2half_rn((v - hf) * SC_UP);
    }
}

// ---------------------------------------------------------------------------
// mma.sync fp16 GEMM: 128x128 tile, 256 threads (warp grid 4x2), K-chunk 32,
// double-buffered cp.async. 3 MMA pairs.
// MODE 0 (proj/out): pairs (A0,B0),(A1,B1),(A2,B0)   [A={h,h_dn,m}, B={h,m_up}]
// MODE 1 (S):        pairs (A0,B0),(A0,B1),(A1,B0)   [A={h,m},      B={h,m}]
// EPI: 0=QK (bias+transpose+2split), 1=V (bias+3plane), 2=S (transpose fp32),
//      3=OUT (x + gamma*acc)
// ---------------------------------------------------------------------------
#define TSTRIDE 40                       // halfs per smem row
#define TILEB   (128 * TSTRIDE * 2)      // 10240 bytes per tile

template<int TA, int TB, int MODE, int EPI>
__global__ __launch_bounds__(256, 1) void gemm_mma(
    const h16* __restrict__ A0, const h16* __restrict__ A1, const h16* __restrict__ A2,
    const h16* __restrict__ B0, const h16* __restrict__ B1,
    long aStride, long bStride, int Kdim,
    const float* __restrict__ bias,
    const float* __restrict__ Xres, const float* __restrict__ gammap,
    void* O0, void* O1, void* O2)
{
    constexpr int NT = TA + TB;
    constexpr int NP = 3;
    constexpr int AIx[3] = {0, MODE ? 0 : 1, MODE ? 1 : 2};
    constexpr int BIx[3] = {0, 1, 0};

    extern __shared__ char smem[];
    const uint32_t sb = smem_u32(smem);
    const int tid  = threadIdx.x;
    const int lane = tid & 31;
    const int wid  = tid >> 5;
    const int wm   = wid & 3;
    const int wn   = wid >> 2;

    const size_t aOff = (size_t)blockIdx.z * aStride + (size_t)blockIdx.y * 128 * Kdim;
    const size_t bOff = (size_t)blockIdx.z * bStride + (size_t)blockIdx.x * 128 * Kdim;
    const h16* tp[NT];
    tp[0] = A0 + aOff;
    if (TA > 1) tp[1] = A1 + aOff;
    if (TA > 2) tp[2] = A2 + aOff;
    tp[TA] = B0 + bOff;
    tp[TA + 1] = B1 + bOff;

    const int nc = Kdim >> 5;

    auto load_chunk = [&](int c) {
        const uint32_t sbase = sb + (uint32_t)(c & 1) * NT * TILEB;
        const int k0 = c << 5;
#pragma unroll
        for (int t = 0; t < NT; t++) {
            const h16* gp = tp[t] + k0;
            const uint32_t tb = sbase + t * TILEB;
#pragma unroll
            for (int i = 0; i < 2; i++) {
                const int idx = i * 256 + tid;
                const int r = idx >> 2, q = idx & 3;
                cp16(tb + r * (TSTRIDE * 2) + q * 16, gp + (size_t)r * Kdim + q * 8);
            }
        }
        asm volatile("cp.async.commit_group;" ::: "memory");
    };

    float acc[2][8][4];
#pragma unroll
    for (int mt = 0; mt < 2; mt++)
#pragma unroll
        for (int nt = 0; nt < 8; nt++)
#pragma unroll
            for (int e = 0; e < 4; e++) acc[mt][nt][e] = 0.f;

    const uint32_t aAddrOff = (uint32_t)(wm * 32 + (lane & 15)) * (TSTRIDE * 2)
                            + (uint32_t)(lane >> 4) * 16;
    const uint32_t bAddrOff = (uint32_t)(wn * 64 + (lane & 7) + ((lane >> 4) & 1) * 8) * (TSTRIDE * 2)
                            + (uint32_t)((lane >> 3) & 1) * 16;

    load_chunk(0);
    for (int c = 0; c < nc; c++) {
        if (c + 1 < nc) {
            load_chunk(c + 1);
            asm volatile("cp.async.wait_group 1;" ::: "memory");
        } else {
            asm volatile("cp.async.wait_group 0;" ::: "memory");
        }
        __syncthreads();

        const uint32_t sbase = sb + (uint32_t)(c & 1) * NT * TILEB;
#pragma unroll
        for (int kk = 0; kk < 2; kk++) {
            uint32_t af[TA][2][4];
            uint32_t bfr[TB][4][4];
#pragma unroll
            for (int t = 0; t < TA; t++)
#pragma unroll
                for (int mt = 0; mt < 2; mt++)
                    ldsm_x4(af[t][mt],
                            sbase + t * TILEB + aAddrOff + (uint32_t)mt * 16 * (TSTRIDE * 2) + kk * 32);
#pragma unroll
            for (int t = 0; t < TB; t++)
#pragma unroll
                for (int p = 0; p < 4; p++)
                    ldsm_x4(bfr[t][p],
                            sbase + (TA + t) * TILEB + bAddrOff + (uint32_t)p * 16 * (TSTRIDE * 2) + kk * 32);
#pragma unroll
            for (int p = 0; p < NP; p++)
#pragma unroll
                for (int mt = 0; mt < 2; mt++)
#pragma unroll
                    for (int pq = 0; pq < 4; pq++) {
                        mma16816(acc[mt][pq * 2 + 0], af[AIx[p]][mt], &bfr[BIx[p]][pq][0]);
                        mma16816(acc[mt][pq * 2 + 1], af[AIx[p]][mt], &bfr[BIx[p]][pq][2]);
                    }
        }
        __syncthreads();
    }

    // -----------------------------------------------------------------------
    const int fr = wm * 32 + (lane >> 2);
    const int fc = wn * 64 + (lane & 3) * 2;

    if (EPI == 1) {
        h16* q0 = (h16*)O0; h16* q1 = (h16*)O1; h16* q2 = (h16*)O2;
#pragma unroll
        for (int mt = 0; mt < 2; mt++)
#pragma unroll
            for (int nt = 0; nt < 8; nt++)
#pragma unroll
                for (int h = 0; h < 2; h++) {
                    const int row = fr + mt * 16 + h * 8;
                    const int col = fc + nt * 8;
                    const int gcol = blockIdx.x * 128 + col;
                    float v0 = acc[mt][nt][h * 2 + 0] + bias[gcol];
                    float v1 = acc[mt][nt][h * 2 + 1] + bias[gcol + 1];
                    float h0 = __half2float(__float2half_rn(v0));
                    float h1 = __half2float(__float2half_rn(v1));
                    const size_t e = ((size_t)blockIdx.y * 128 + row) * CCH + gcol;
                    *(uint32_t*)(q0 + e) = pack_h2(h0, h1);
                    *(uint32_t*)(q1 + e) = pack_h2(h0 * SC_DN, h1 * SC_DN);
                    *(uint32_t*)(q2 + e) = pack_h2(v0 - h0, v1 - h1);
                }
    } else if (EPI == 3) {
        const float g = gammap[0];
        float* Op = (float*)O0;
#pragma unroll
        for (int mt = 0; mt < 2; mt++)
#pragma unroll
            for (int nt = 0; nt < 8; nt++)
#pragma unroll
                for (int h = 0; h < 2; h++) {
                    const int row = fr + mt * 16 + h * 8;
                    const int col = fc + nt * 8;
                    const size_t nrow = (size_t)blockIdx.z * NPIX + (size_t)blockIdx.y * 128 + row;
                    const size_t e = nrow * CCH + blockIdx.x * 128 + col;
                    const float2 xi = *(const float2*)(Xres + e);
                    float2 o;
                    o.x = xi.x + g * acc[mt][nt][h * 2 + 0];
                    o.y = xi.y + g * acc[mt][nt][h * 2 + 1];
                    *(float2*)(Op + e) = o;
                }
    } else {
        // transpose epilogues via fp32 smem buffer [128][132]
        float* sbuf = (float*)smem;
#pragma unroll
        for (int mt = 0; mt < 2; mt++)
#pragma unroll
            for (int nt = 0; nt < 8; nt++)
#pragma unroll
                for (int h = 0; h < 2; h++) {
                    const int row = fr + mt * 16 + h * 8;
                    const int col = fc + nt * 8;
                    float v0 = acc[mt][nt][h * 2 + 0];
                    float v1 = acc[mt][nt][h * 2 + 1];
                    if (EPI == 0) {
                        v0 += bias[blockIdx.x * 128 + col];
                        v1 += bias[blockIdx.x * 128 + col + 1];
                    }
                    sbuf[row * 132 + col]     = v0;
                    sbuf[row * 132 + col + 1] = v1;
                }
        __syncthreads();

        const int pr      = (tid & 63) * 2;
        const int quarter = tid >> 6;
        if (EPI == 0) {
            const int bch = (blockIdx.y * 128) >> 12;
            const int n0  = (blockIdx.y * 128) & 4095;
            h16* q0 = (h16*)O0; h16* q1 = (h16*)O1;
#pragma unroll 8
            for (int ff = 0; ff < 32; ff++) {
                const int fl = quarter * 32 + ff;
                const float v0 = sbuf[pr * 132 + fl];
                const float v1 = sbuf[(pr + 1) * 132 + fl];
                float h0 = __half2float(__float2half_rn(v0));
                float h1 = __half2float(__float2half_rn(v1));
                const size_t e = ((size_t)bch * CCH + blockIdx.x * 128 + fl) * NPIX + n0 + pr;
                *(uint32_t*)(q0 + e) = pack_h2(h0, h1);
                *(uint32_t*)(q1 + e) = pack_h2(v0 - h0, v1 - h1);
            }
        } else { // EPI == 2
            float* st = (float*)O0;
#pragma unroll 8
            for (int dd = 0; dd < 32; dd++) {
                const int dl = quarter * 32 + dd;
                float2 o;
                o.x = sbuf[pr * 132 + dl];
                o.y = sbuf[(pr + 1) * 132 + dl];
                const size_t e = (size_t)blockIdx.z * SZW +
                                 (size_t)(blockIdx.x * 128 + dl) * CCH +
                                 blockIdx.y * 128 + pr;
                *(float2*)(st + e) = o;
            }
        }
    }
}

// ---------------------------------------------------------------------------
// Column softmax on S_t [d][c] (softmax over d), writes {h, m*2^11} planes
// ---------------------------------------------------------------------------
__global__ __launch_bounds__(128) void softmax_col_kernel()
{
    const int b = blockIdx.y;
    const int c = blockIdx.x * 128 + threadIdx.x;
    const float* S = g_st + (size_t)b * SZW;
    h16* a0 = g_at + (size_t)b * SZW;
    h16* a1 = g_at + SZS + (size_t)b * SZW;

    float m = -1e30f;
    for (int d = 0; d < CCH; d++) m = fmaxf(m, S[(size_t)d * CCH + c]);
    float s = 0.f;
    for (int d = 0; d < CCH; d++) s += expf(S[(size_t)d * CCH + c] - m);
    const float inv = 1.0f / s;
    for (int d = 0; d < CCH; d++) {
        const float p = expf(S[(size_t)d * CCH + c] - m) * inv;
        const float hf = __half2float(__float2half_rn(p));
        a0[(size_t)d * CCH + c] = __float2half_rn(hf);
        a1[(size_t)d * CCH + c] = __float2half_rn((p - hf) * SC_UP);
    }
}

// ---------------------------------------------------------------------------
extern "C" void kernel_launch(void* const* d_in, const int* in_sizes, int n_in,
                              void* d_out, int out_size)
{
    const float* x     = (const float*)d_in[0];
    const float* wq    = (const float*)d_in[1];
    const float* bq    = (const float*)d_in[2];
    const float* wk    = (const float*)d_in[3];
    const float* bk    = (const float*)d_in[4];
    const float* wv    = (const float*)d_in[5];
    const float* bv    = (const float*)d_in[6];
    const float* gamma = (const float*)d_in[7];
    float* out = (float*)d_out;

    void* p;
    cudaGetSymbolAddress(&p, g_x);  h16* xs = (h16*)p;
    cudaGetSymbolAddress(&p, g_wt); h16* wt = (h16*)p;
    cudaGetSymbolAddress(&p, g_qt); h16* qt = (h16*)p;
    cudaGetSymbolAddress(&p, g_kt); h16* kt = (h16*)p;
    cudaGetSymbolAddress(&p, g_v);  h16* vs = (h16*)p;
    cudaGetSymbolAddress(&p, g_st); float* st = (float*)p;
    cudaGetSymbolAddress(&p, g_at); h16* at = (h16*)p;

    const int SM5 = 2 * 5 * TILEB;   // 102400
    const int SM4 = 2 * 4 * TILEB;   // 81920
    cudaFuncSetAttribute(gemm_mma<3,2,0,0>, cudaFuncAttributeMaxDynamicSharedMemorySize, SM5);
    cudaFuncSetAttribute(gemm_mma<3,2,0,1>, cudaFuncAttributeMaxDynamicSharedMemorySize, SM5);
    cudaFuncSetAttribute(gemm_mma<2,2,1,2>, cudaFuncAttributeMaxDynamicSharedMemorySize, SM4);
    cudaFuncSetAttribute(gemm_mma<3,2,0,3>, cudaFuncAttributeMaxDynamicSharedMemorySize, SM5);

    // 1) splits
    split_x_kernel<<<(unsigned)(SZX / 4 / 256), 256>>>(x);
    split_w_kernel<<<dim3(16, 16, 3), 256>>>(wq, wk, wv);

    // 2) Q = X@Wq^T -> q_t {h,m}
    gemm_mma<3,2,0,0><<<dim3(4, 512, 1), 256, SM5>>>(
        xs, xs + SZX, xs + 2*SZX,
        wt + 0*2*SZW, wt + 0*2*SZW + SZW,
        0, 0, CCH, bq, nullptr, nullptr,
        qt, qt + SZX, nullptr);
    // 3) K
    gemm_mma<3,2,0,0><<<dim3(4, 512, 1), 256, SM5>>>(
        xs, xs + SZX, xs + 2*SZX,
        wt + 1*2*SZW, wt + 1*2*SZW + SZW,
        0, 0, CCH, bk, nullptr, nullptr,
        kt, kt + SZX, nullptr);
    // 4) V -> v {h, h_dn, m}
    gemm_mma<3,2,0,1><<<dim3(4, 512, 1), 256, SM5>>>(
        xs, xs + SZX, xs + 2*SZX,
        wt + 2*2*SZW, wt + 2*2*SZW + SZW,
        0, 0, CCH, bv, nullptr, nullptr,
        vs, vs + SZX, vs + 2*SZX);
    // 5) S = Q^T K per batch (Kdim=4096) -> S_t fp32
    gemm_mma<2,2,1,2><<<dim3(4, 4, BATCH), 256, SM4>>>(
        qt, qt + SZX, nullptr,
        kt, kt + SZX,
        (long)CCH * NPIX, (long)CCH * NPIX, NPIX, nullptr, nullptr, nullptr,
        st, nullptr, nullptr);
    // 6) column softmax -> a_t {h, m_up}
    softmax_col_kernel<<<dim3(4, BATCH), 128>>>();
    // 7) out = x + gamma * V @ A
    gemm_mma<3,2,0,3><<<dim3(4, 32, BATCH), 256, SM5>>>(
        vs, vs + SZX, vs + 2*SZX,
        at, at + SZS,
        (long)NPIX * CCH, (long)CCH * CCH, CCH, nullptr, x, gamma,
        out, nullptr, nullptr);
}

// round 6
// speedup vs baseline: 2.2061x; 1.3191x over previous
#include <cuda_runtime.h>
#include <cuda_fp16.h>
#include <cstdint>
#include <cstddef>
#include <cstring>

#define BATCH 16
#define NPIX  4096
#define CCH   512
#define MTOT  (BATCH * NPIX)   // 65536

typedef __half h16;

#define SZX  ((size_t)MTOT * CCH)        // 33,554,432 elems
#define SZW  ((size_t)CCH * CCH)         // 262,144
#define SZS  ((size_t)BATCH * CCH * CCH) // 4,194,304

// fp16 split planes (scaled plane derived in registers, not stored)
__device__ h16   g_x [2 * SZX];          // x: {h, m}
__device__ h16   g_wt[3 * 2 * SZW];      // per matrix {h, m*2^11}, transposed
__device__ h16   g_qt[2 * SZX];          // q_t per batch [c][n]: {h, m}
__device__ h16   g_kt[2 * SZX];          // k_t: {h, m}
__device__ h16   g_v [2 * SZX];          // v [n][c]: {h, m}
__device__ float g_st[SZS];              // S_t fp32 per batch [d][c]
__device__ h16   g_at[2 * SZS];          // a_t [d][c]: {h, m*2^11}

#define SC_UP 2048.0f         // 2^11
#define HALF2_2PM11 0x10001000u   // half2(2^-11, 2^-11)

// ---------------------------------------------------------------------------
__device__ __forceinline__ uint32_t smem_u32(const void* p) {
    uint32_t a;
    asm("{ .reg .u64 t; cvta.to.shared.u64 t, %1; cvt.u32.u64 %0, t; }"
        : "=r"(a) : "l"(p));
    return a;
}

__device__ __forceinline__ void cp16(uint32_t dst, const void* src) {
    asm volatile("cp.async.cg.shared.global [%0], [%1], 16;" :: "r"(dst), "l"(src) : "memory");
}

__device__ __forceinline__ void ldsm_x4(uint32_t* r, uint32_t addr) {
    asm volatile("ldmatrix.sync.aligned.m8n8.x4.shared.b16 {%0,%1,%2,%3}, [%4];"
        : "=r"(r[0]), "=r"(r[1]), "=r"(r[2]), "=r"(r[3]) : "r"(addr));
}

__device__ __forceinline__ void mma16816(float* c, const uint32_t* a, const uint32_t* b) {
    asm volatile(
        "mma.sync.aligned.m16n8k16.row.col.f32.f16.f16.f32 "
        "{%0,%1,%2,%3}, {%4,%5,%6,%7}, {%8,%9}, {%0,%1,%2,%3};"
        : "+f"(c[0]), "+f"(c[1]), "+f"(c[2]), "+f"(c[3])
        : "r"(a[0]), "r"(a[1]), "r"(a[2]), "r"(a[3]), "r"(b[0]), "r"(b[1]));
}

__device__ __forceinline__ uint32_t hmul2c(uint32_t a, uint32_t c) {
    uint32_t r;
    asm("mul.rn.f16x2 %0, %1, %2;" : "=r"(r) : "r"(a), "r"(c));
    return r;
}

__device__ __forceinline__ uint32_t pack_h2(float a, float b) {
    __half2 t = __floats2half2_rn(a, b);
    uint32_t u; memcpy(&u, &t, 4); return u;
}

// ---------------------------------------------------------------------------
// Split kernels
// ---------------------------------------------------------------------------
__global__ __launch_bounds__(256) void split_x_kernel(const float* __restrict__ x)
{
    size_t i4 = (size_t)blockIdx.x * 256 + threadIdx.x;
    const float4 v = ((const float4*)x)[i4];
    float vv[4] = {v.x, v.y, v.z, v.w};
    float hf[4], mf[4];
#pragma unroll
    for (int i = 0; i < 4; i++) {
        hf[i] = __half2float(__float2half_rn(vv[i]));
        mf[i] = vv[i] - hf[i];
    }
    uint32_t* o0 = (uint32_t*)g_x;
    uint32_t* o1 = (uint32_t*)(g_x + SZX);
    o0[i4*2] = pack_h2(hf[0], hf[1]); o0[i4*2+1] = pack_h2(hf[2], hf[3]);
    o1[i4*2] = pack_h2(mf[0], mf[1]); o1[i4*2+1] = pack_h2(mf[2], mf[3]);
}

__global__ __launch_bounds__(256) void split_w_kernel(
    const float* __restrict__ wq, const float* __restrict__ wk, const float* __restrict__ wv)
{
    __shared__ float tile[32][33];
    const int z = blockIdx.z;
    const float* w = (z == 0) ? wq : (z == 1) ? wk : wv;
    h16* out = g_wt + (size_t)z * 2 * SZW;
    const int f0 = blockIdx.x * 32, c0 = blockIdx.y * 32;
    const int tx = threadIdx.x & 31, ty = threadIdx.x >> 5;
#pragma unroll
    for (int k = 0; k < 4; k++)
        tile[ty + 8*k][tx] = w[(size_t)(c0 + ty + 8*k) * CCH + f0 + tx];
    __syncthreads();
#pragma unroll
    for (int k = 0; k < 4; k++) {
        const int fl = ty + 8*k;
        float v = tile[tx][fl];
        float hf = __half2float(__float2half_rn(v));
        size_t idx = (size_t)(f0 + fl) * CCH + c0 + tx;
        out[idx]       = __float2half_rn(hf);
        out[SZW + idx] = __float2half_rn((v - hf) * SC_UP);
    }
}

// ---------------------------------------------------------------------------
// mma.sync fp16 GEMM: 128x128 tile, 256 threads (warp grid 4x2), K-chunk 32,
// double-buffered cp.async, NT=4 tiles (A={h,m}, B={h,b1}), 3 pairs:
//   (A0,B0), (MODE0 ? A0*2^-11 : A0, B1), (A1,B0)
// EPI: 0=QK (bias+transpose+2split), 1=V (bias+2split direct), 2=S (transpose
//      fp32), 3=OUT (x + gamma*acc)
// ---------------------------------------------------------------------------
#define TSTRIDE 40                       // halfs per smem row
#define TILEB   (128 * TSTRIDE * 2)      // 10240 bytes per tile

template<int MODE, int EPI>
__global__ __launch_bounds__(256, 2) void gemm_mma(
    const h16* __restrict__ A0, const h16* __restrict__ A1,
    const h16* __restrict__ B0, const h16* __restrict__ B1,
    long aStride, long bStride, int Kdim,
    const float* __restrict__ bias,
    const float* __restrict__ Xres, const float* __restrict__ gammap,
    void* O0, void* O1)
{
    extern __shared__ char smem[];
    const uint32_t sb = smem_u32(smem);
    const int tid  = threadIdx.x;
    const int lane = tid & 31;
    const int wid  = tid >> 5;
    const int wm   = wid & 3;
    const int wn   = wid >> 2;

    const size_t aOff = (size_t)blockIdx.z * aStride + (size_t)blockIdx.y * 128 * Kdim;
    const size_t bOff = (size_t)blockIdx.z * bStride + (size_t)blockIdx.x * 128 * Kdim;
    const h16* tp[4];
    tp[0] = A0 + aOff;
    tp[1] = A1 + aOff;
    tp[2] = B0 + bOff;
    tp[3] = B1 + bOff;

    const int nc = Kdim >> 5;

    auto load_chunk = [&](int c) {
        const uint32_t sbase = sb + (uint32_t)(c & 1) * 4 * TILEB;
        const int k0 = c << 5;
#pragma unroll
        for (int t = 0; t < 4; t++) {
            const h16* gp = tp[t] + k0;
            const uint32_t tb = sbase + t * TILEB;
#pragma unroll
            for (int i = 0; i < 2; i++) {
                const int idx = i * 256 + tid;
                const int r = idx >> 2, q = idx & 3;
                cp16(tb + r * (TSTRIDE * 2) + q * 16, gp + (size_t)r * Kdim + q * 8);
            }
        }
        asm volatile("cp.async.commit_group;" ::: "memory");
    };

    float acc[2][8][4];
#pragma unroll
    for (int mt = 0; mt < 2; mt++)
#pragma unroll
        for (int nt = 0; nt < 8; nt++)
#pragma unroll
            for (int e = 0; e < 4; e++) acc[mt][nt][e] = 0.f;

    const uint32_t aAddrOff = (uint32_t)(wm * 32 + (lane & 15)) * (TSTRIDE * 2)
                            + (uint32_t)(lane >> 4) * 16;
    const uint32_t bAddrOff = (uint32_t)(wn * 64 + (lane & 7) + ((lane >> 4) & 1) * 8) * (TSTRIDE * 2)
                            + (uint32_t)((lane >> 3) & 1) * 16;

    load_chunk(0);
    for (int c = 0; c < nc; c++) {
        if (c + 1 < nc) {
            load_chunk(c + 1);
            asm volatile("cp.async.wait_group 1;" ::: "memory");
        } else {
            asm volatile("cp.async.wait_group 0;" ::: "memory");
        }
        __syncthreads();

        const uint32_t sbase = sb + (uint32_t)(c & 1) * 4 * TILEB;
#pragma unroll
        for (int kk = 0; kk < 2; kk++) {
            uint32_t af[2][2][4];     // [tile][mt][reg]
#pragma unroll
            for (int t = 0; t < 2; t++)
#pragma unroll
                for (int mt = 0; mt < 2; mt++)
                    ldsm_x4(af[t][mt],
                            sbase + t * TILEB + aAddrOff + (uint32_t)mt * 16 * (TSTRIDE * 2) + kk * 32);
            uint32_t afs[2][4];       // A0 scaled by 2^-11 (MODE 0 only)
            if (MODE == 0) {
#pragma unroll
                for (int mt = 0; mt < 2; mt++)
#pragma unroll
                    for (int r = 0; r < 4; r++)
                        afs[mt][r] = hmul2c(af[0][mt][r], HALF2_2PM11);
            }
#pragma unroll
            for (int pq = 0; pq < 4; pq++) {
                uint32_t b0[4], b1[4];
                ldsm_x4(b0, sbase + 2 * TILEB + bAddrOff + (uint32_t)pq * 16 * (TSTRIDE * 2) + kk * 32);
                ldsm_x4(b1, sbase + 3 * TILEB + bAddrOff + (uint32_t)pq * 16 * (TSTRIDE * 2) + kk * 32);
#pragma unroll
                for (int mt = 0; mt < 2; mt++) {
                    float* c0 = acc[mt][pq * 2 + 0];
                    float* c1 = acc[mt][pq * 2 + 1];
                    mma16816(c0, af[0][mt], &b0[0]);
                    mma16816(c1, af[0][mt], &b0[2]);
                    const uint32_t* a2 = (MODE == 0) ? afs[mt] : af[0][mt];
                    mma16816(c0, a2, &b1[0]);
                    mma16816(c1, a2, &b1[2]);
                    mma16816(c0, af[1][mt], &b0[0]);
                    mma16816(c1, af[1][mt], &b0[2]);
                }
            }
        }
        __syncthreads();
    }

    // -----------------------------------------------------------------------
    const int fr = wm * 32 + (lane >> 2);
    const int fc = wn * 64 + (lane & 3) * 2;

    if (EPI == 1) {
        h16* q0 = (h16*)O0; h16* q1 = (h16*)O1;
#pragma unroll
        for (int mt = 0; mt < 2; mt++)
#pragma unroll
            for (int nt = 0; nt < 8; nt++)
#pragma unroll
                for (int h = 0; h < 2; h++) {
                    const int row = fr + mt * 16 + h * 8;
                    const int col = fc + nt * 8;
                    const int gcol = blockIdx.x * 128 + col;
                    float v0 = acc[mt][nt][h * 2 + 0] + bias[gcol];
                    float v1 = acc[mt][nt][h * 2 + 1] + bias[gcol + 1];
                    float h0 = __half2float(__float2half_rn(v0));
                    float h1 = __half2float(__float2half_rn(v1));
                    const size_t e = ((size_t)blockIdx.y * 128 + row) * CCH + gcol;
                    *(uint32_t*)(q0 + e) = pack_h2(h0, h1);
                    *(uint32_t*)(q1 + e) = pack_h2(v0 - h0, v1 - h1);
                }
    } else if (EPI == 3) {
        const float g = gammap[0];
        float* Op = (float*)O0;
#pragma unroll
        for (int mt = 0; mt < 2; mt++)
#pragma unroll
            for (int nt = 0; nt < 8; nt++)
#pragma unroll
                for (int h = 0; h < 2; h++) {
                    const int row = fr + mt * 16 + h * 8;
                    const int col = fc + nt * 8;
                    const size_t nrow = (size_t)blockIdx.z * NPIX + (size_t)blockIdx.y * 128 + row;
                    const size_t e = nrow * CCH + blockIdx.x * 128 + col;
                    const float2 xi = *(const float2*)(Xres + e);
                    float2 o;
                    o.x = xi.x + g * acc[mt][nt][h * 2 + 0];
                    o.y = xi.y + g * acc[mt][nt][h * 2 + 1];
                    *(float2*)(Op + e) = o;
                }
    } else {
        // transpose epilogues via fp32 smem buffer [128][132]
        float* sbuf = (float*)smem;
#pragma unroll
        for (int mt = 0; mt < 2; mt++)
#pragma unroll
            for (int nt = 0; nt < 8; nt++)
#pragma unroll
                for (int h = 0; h < 2; h++) {
                    const int row = fr + mt * 16 + h * 8;
                    const int col = fc + nt * 8;
                    float v0 = acc[mt][nt][h * 2 + 0];
                    float v1 = acc[mt][nt][h * 2 + 1];
                    if (EPI == 0) {
                        v0 += bias[blockIdx.x * 128 + col];
                        v1 += bias[blockIdx.x * 128 + col + 1];
                    }
                    sbuf[row * 132 + col]     = v0;
                    sbuf[row * 132 + col + 1] = v1;
                }
        __syncthreads();

        const int pr      = (tid & 63) * 2;
        const int quarter = tid >> 6;
        if (EPI == 0) {
            const int bch = (blockIdx.y * 128) >> 12;
            const int n0  = (blockIdx.y * 128) & 4095;
            h16* q0 = (h16*)O0; h16* q1 = (h16*)O1;
#pragma unroll 8
            for (int ff = 0; ff < 32; ff++) {
                const int fl = quarter * 32 + ff;
                const float v0 = sbuf[pr * 132 + fl];
                const float v1 = sbuf[(pr + 1) * 132 + fl];
                float h0 = __half2float(__float2half_rn(v0));
                float h1 = __half2float(__float2half_rn(v1));
                const size_t e = ((size_t)bch * CCH + blockIdx.x * 128 + fl) * NPIX + n0 + pr;
                *(uint32_t*)(q0 + e) = pack_h2(h0, h1);
                *(uint32_t*)(q1 + e) = pack_h2(v0 - h0, v1 - h1);
            }
        } else { // EPI == 2
            float* st = (float*)O0;
#pragma unroll 8
            for (int dd = 0; dd < 32; dd++) {
                const int dl = quarter * 32 + dd;
                float2 o;
                o.x = sbuf[pr * 132 + dl];
                o.y = sbuf[(pr + 1) * 132 + dl];
                const size_t e = (size_t)blockIdx.z * SZW +
                                 (size_t)(blockIdx.x * 128 + dl) * CCH +
                                 blockIdx.y * 128 + pr;
                *(float2*)(st + e) = o;
            }
        }
        __syncthreads();   // sbuf reused by 2nd resident CTA? no — per-CTA smem; but protects loop reuse pattern anyway
    }
}

// ---------------------------------------------------------------------------
// Column softmax on S_t [d][c] (softmax over d), writes {h, m*2^11} planes
// ---------------------------------------------------------------------------
__global__ __launch_bounds__(128) void softmax_col_kernel()
{
    const int b = blockIdx.y;
    const int c = blockIdx.x * 128 + threadIdx.x;
    const float* S = g_st + (size_t)b * SZW;
    h16* a0 = g_at + (size_t)b * SZW;
    h16* a1 = g_at + SZS + (size_t)b * SZW;

    float m = -1e30f;
    for (int d = 0; d < CCH; d++) m = fmaxf(m, S[(size_t)d * CCH + c]);
    float s = 0.f;
    for (int d = 0; d < CCH; d++) s += expf(S[(size_t)d * CCH + c] - m);
    const float inv = 1.0f / s;
    for (int d = 0; d < CCH; d++) {
        const float p = expf(S[(size_t)d * CCH + c] - m) * inv;
        const float hf = __half2float(__float2half_rn(p));
        a0[(size_t)d * CCH + c] = __float2half_rn(hf);
        a1[(size_t)d * CCH + c] = __float2half_rn((p - hf) * SC_UP);
    }
}

// ---------------------------------------------------------------------------
extern "C" void kernel_launch(void* const* d_in, const int* in_sizes, int n_in,
                              void* d_out, int out_size)
{
    const float* x     = (const float*)d_in[0];
    const float* wq    = (const float*)d_in[1];
    const float* bq    = (const float*)d_in[2];
    const float* wk    = (const float*)d_in[3];
    const float* bk    = (const float*)d_in[4];
    const float* wv    = (const float*)d_in[5];
    const float* bv    = (const float*)d_in[6];
    const float* gamma = (const float*)d_in[7];
    float* out = (float*)d_out;

    void* p;
    cudaGetSymbolAddress(&p, g_x);  h16* xs = (h16*)p;
    cudaGetSymbolAddress(&p, g_wt); h16* wt = (h16*)p;
    cudaGetSymbolAddress(&p, g_qt); h16* qt = (h16*)p;
    cudaGetSymbolAddress(&p, g_kt); h16* kt = (h16*)p;
    cudaGetSymbolAddress(&p, g_v);  h16* vs = (h16*)p;
    cudaGetSymbolAddress(&p, g_st); float* st = (float*)p;
    cudaGetSymbolAddress(&p, g_at); h16* at = (h16*)p;

    const int SMEM = 2 * 4 * TILEB;   // 81920
    cudaFuncSetAttribute(gemm_mma<0,0>, cudaFuncAttributeMaxDynamicSharedMemorySize, SMEM);
    cudaFuncSetAttribute(gemm_mma<0,1>, cudaFuncAttributeMaxDynamicSharedMemorySize, SMEM);
    cudaFuncSetAttribute(gemm_mma<1,2>, cudaFuncAttributeMaxDynamicSharedMemorySize, SMEM);
    cudaFuncSetAttribute(gemm_mma<0,3>, cudaFuncAttributeMaxDynamicSharedMemorySize, SMEM);

    // 1) splits
    split_x_kernel<<<(unsigned)(SZX / 4 / 256), 256>>>(x);
    split_w_kernel<<<dim3(16, 16, 3), 256>>>(wq, wk, wv);

    // 2) Q = X@Wq^T -> q_t {h,m}
    gemm_mma<0,0><<<dim3(4, 512, 1), 256, SMEM>>>(
        xs, xs + SZX, wt + 0*2*SZW, wt + 0*2*SZW + SZW,
        0, 0, CCH, bq, nullptr, nullptr, qt, qt + SZX);
    // 3) K
    gemm_mma<0,0><<<dim3(4, 512, 1), 256, SMEM>>>(
        xs, xs + SZX, wt + 1*2*SZW, wt + 1*2*SZW + SZW,
        0, 0, CCH, bk, nullptr, nullptr, kt, kt + SZX);
    // 4) V -> v {h, m}
    gemm_mma<0,1><<<dim3(4, 512, 1), 256, SMEM>>>(
        xs, xs + SZX, wt + 2*2*SZW, wt + 2*2*SZW + SZW,
        0, 0, CCH, bv, nullptr, nullptr, vs, vs + SZX);
    // 5) S = Q^T K per batch (Kdim=4096) -> S_t fp32
    gemm_mma<1,2><<<dim3(4, 4, BATCH), 256, SMEM>>>(
        qt, qt + SZX, kt, kt + SZX,
        (long)CCH * NPIX, (long)CCH * NPIX, NPIX, nullptr, nullptr, nullptr,
        st, nullptr);
    // 6) column softmax -> a_t {h, m_up}
    softmax_col_kernel<<<dim3(4, BATCH), 128>>>();
    // 7) out = x + gamma * V @ A
    gemm_mma<0,3><<<dim3(4, 32, BATCH), 256, SMEM>>>(
        vs, vs + SZX, at, at + SZS,
        (long)NPIX * CCH, (long)CCH * CCH, CCH, nullptr, x, gamma,
        out, nullptr);
}